// round 4
// baseline (speedup 1.0000x reference)
#include <cuda_runtime.h>
#include <cstdint>
#include <cstddef>

#define B_ 4096
#define T_ 168
#define D_ 64
#define H_ 128
#define G_ 384   // 3*H

typedef unsigned long long ull;

// ---------------------------------------------------------------------------
// Packed fp32x2 helpers: one FFMA2 = 2 fp32 FMAs per issue slot.
// K accumulated pairwise (even k in .lo, odd k in .hi), horizontal lo+hi last.
// ---------------------------------------------------------------------------
__device__ __forceinline__ ull ffma2(ull a, ull b, ull c) {
    ull d;
    asm("fma.rn.f32x2 %0, %1, %2, %3;" : "=l"(d) : "l"(a), "l"(b), "l"(c));
    return d;
}
__device__ __forceinline__ float f2sum(ull v) {
    float lo = __uint_as_float((unsigned)(v & 0xffffffffull));
    float hi = __uint_as_float((unsigned)(v >> 32));
    return lo + hi;
}
__device__ __forceinline__ float fast_sigmoid(float x) {
    return __fdividef(1.f, 1.f + __expf(-x));
}
__device__ __forceinline__ float fast_tanh(float x) {
    return __fdividef(2.f, 1.f + __expf(-2.f * x)) - 1.f;
}

__device__ __forceinline__ void cpasync16(void* smem_dst, const void* gsrc) {
    unsigned saddr = (unsigned)__cvta_generic_to_shared(smem_dst);
    asm volatile("cp.async.ca.shared.global [%0], [%1], 16;\n" :: "r"(saddr), "l"(gsrc));
}
#define CP_COMMIT() asm volatile("cp.async.commit_group;\n" ::: "memory")
#define CP_WAIT(n)  asm volatile("cp.async.wait_group %0;\n" :: "n"(n) : "memory")

// Scratch: gx[t][b][g] fp32, ~1.01 GB device global.
__device__ float g_gx[(size_t)T_ * B_ * G_];

// ---------------------------------------------------------------------------
// Kernel A: gx[t][b][g] = feats[b][t][:] . W_ih[g][:D] + b_ih[g]
// 148 blocks = 4 gate-slices (96 gates) x 37 tile-walkers, 512 threads.
// Warps: 4 row-blocks x 4 gate-blocks. Thread tile 4 rows x 6 gates.
// f loads: 8 distinct rows spaced 4 banks -> conflict-free, 4-way bcast.
// W loads: 4 addrs spaced 24 banks -> conflict-free, 8-way bcast.
// Output staged in smem then stored as full 384B rows (3 full lines/row).
// ---------------------------------------------------------------------------
#define A_NT   96
#define A_MT   128
#define A_PAD  68
#define A_OP   104   // sOut row stride (floats)

__global__ void __launch_bounds__(512, 1)
gx_kernel(const float* __restrict__ feats, const float* __restrict__ W_ih,
          const float* __restrict__ b_ih)
{
    extern __shared__ float smemA[];
    float* sW   = smemA;                        // 96*68  = 6528
    float* sF0  = sW + A_NT * A_PAD;            // 128*68 = 8704
    float* sF1  = sF0 + A_MT * A_PAD;           // 8704
    float* sOut = sF1 + A_MT * A_PAD;           // 128*104 = 13312
    float* sB   = sOut + A_MT * A_OP;           // 96

    const int tid  = threadIdx.x;
    const int wid  = tid >> 5;
    const int lane = tid & 31;
    const int rb   = wid >> 2;            // row block 0..3   (32 rows each)
    const int gblk = wid & 3;             // gate block 0..3  (24 gates each)
    const int rg   = lane >> 2;           // 0..7
    const int lg   = lane & 3;            // 0..3
    const int gloc = gblk * 24 + lg * 6;  // thread's first gate (6 gates)

    const int slice = blockIdx.x & 3;
    const int px    = blockIdx.x >> 2;    // 0..36
    const int g_base = slice * A_NT;

    for (int i = tid; i < A_NT * D_; i += 512) {
        int g = i >> 6, d = i & 63;
        sW[g * A_PAD + d] = W_ih[(size_t)(g_base + g) * (D_ + 1) + d];
    }
    for (int i = tid; i < A_NT; i += 512) sB[i] = b_ih[g_base + i];

    const int NTILES = (B_ * T_) / A_MT;  // 5376 (t-major: 32 b-tiles per t)
    float* sF[2] = { sF0, sF1 };

    // prefetch first tile (t-major): tile mt -> t = mt>>5, bb = (mt&31)*128
    {
        int t0 = px >> 5, bb0 = (px & 31) * A_MT;
        for (int i = 0; i < 4; i++) {
            int ci = tid + i * 512;                 // 2048 chunks of 16B
            int row = ci >> 4, seg = ci & 15;
            cpasync16(sF0 + row * A_PAD + seg * 4,
                      feats + ((size_t)(bb0 + row) * T_ + t0) * D_ + seg * 4);
        }
        CP_COMMIT();
    }

    int buf = 0;
    for (int mt = px; mt < NTILES; mt += 37) {
        const int t  = mt >> 5;
        const int bb = (mt & 31) * A_MT;

        int mt_next = mt + 37;
        if (mt_next < NTILES) {
            int tn = mt_next >> 5, bn = (mt_next & 31) * A_MT;
            float* dst = sF[buf ^ 1];
            for (int i = 0; i < 4; i++) {
                int ci = tid + i * 512;
                int row = ci >> 4, seg = ci & 15;
                cpasync16(dst + row * A_PAD + seg * 4,
                          feats + ((size_t)(bn + row) * T_ + tn) * D_ + seg * 4);
            }
            CP_COMMIT();
            CP_WAIT(1);
        } else {
            CP_WAIT(0);
        }
        __syncthreads();   // sF[buf] ready; sOut free (prev STG done)

        const ulonglong2* sF16 = reinterpret_cast<const ulonglong2*>(sF[buf]);
        const ulonglong2* sW16 = reinterpret_cast<const ulonglong2*>(sW);

        ull acc[4][6];
        #pragma unroll
        for (int a = 0; a < 4; a++)
            #pragma unroll
            for (int u = 0; u < 6; u++) acc[a][u] = 0ull;

        #pragma unroll 4
        for (int k4 = 0; k4 < 16; k4++) {
            ulonglong2 f[4];
            #pragma unroll
            for (int rr = 0; rr < 4; rr++)
                f[rr] = sF16[(rb * 32 + rg + rr * 8) * 17 + k4];
            #pragma unroll
            for (int u = 0; u < 6; u++) {
                ulonglong2 w = sW16[(gloc + u) * 17 + k4];
                #pragma unroll
                for (int rr = 0; rr < 4; rr++) {
                    acc[rr][u] = ffma2(f[rr].x, w.x, acc[rr][u]);
                    acc[rr][u] = ffma2(f[rr].y, w.y, acc[rr][u]);
                }
            }
        }

        // stage results (+bias) into sOut[row][gate_local]
        #pragma unroll
        for (int rr = 0; rr < 4; rr++) {
            int row = rb * 32 + rg + rr * 8;
            float* o = &sOut[row * A_OP + gloc];
            #pragma unroll
            for (int v = 0; v < 3; v++) {
                float2 p;
                p.x = f2sum(acc[rr][v * 2 + 0]) + sB[gloc + v * 2 + 0];
                p.y = f2sum(acc[rr][v * 2 + 1]) + sB[gloc + v * 2 + 1];
                *reinterpret_cast<float2*>(o + v * 2) = p;
            }
        }
        __syncthreads();

        // coalesced store: 128 rows x 384B contiguous (3 full lines per row)
        for (int i = 0; i < 6; i++) {
            int ci = tid + i * 512;                 // 3072 float4 chunks
            int row = ci / 24, seg = ci - row * 24;
            float4 v = *reinterpret_cast<const float4*>(&sOut[row * A_OP + seg * 4]);
            *reinterpret_cast<float4*>(
                &g_gx[((size_t)t * B_ + bb + row) * G_ + g_base + seg * 4]) = v;
        }
        buf ^= 1;
        // next iteration's __syncthreads protects sOut & sF reuse
    }
}

// ---------------------------------------------------------------------------
// Kernel B: persistent GRU scan. 128 blocks x 512 threads (16 warps, 4/SMSP
// for latency hiding), 32 batch rows per block. W_hh in smem, pad 132:
// h ull loads 8 addrs spaced 4 banks (conflict-free, 4-way bcast),
// W ull loads 4 addrs spaced 8 banks (conflict-free, 8-way bcast).
// Thread tile: 4 rows x 2 channels x {r,z,n} = 24 f32x2 accumulators.
// gx LDGs issued at loop top, consumed only in the epilogue (~12k cyc later)
// so DRAM latency is hidden under the FMA mainloop.
// ---------------------------------------------------------------------------
#define R_    32
#define SWP   132
#define SWP2  66

__global__ void __launch_bounds__(512, 1)
scan_kernel(const float* __restrict__ h0, const float* __restrict__ y0,
            const float* __restrict__ W_ih, const float* __restrict__ W_hh,
            const float* __restrict__ b_hh, const float* __restrict__ Wo,
            const float* __restrict__ bo, float* __restrict__ out)
{
    extern __shared__ float smem[];
    float* sW   = smem;                 // 384*132 = 50688
    float* sH   = sW + G_ * SWP;        // 32*132  = 4224
    float* sWy  = sH + R_ * SWP;        // 384
    float* sBhh = sWy + G_;             // 384
    float* sWo  = sBhh + G_;            // 128
    float* sY   = sWo + H_;             // 32
    float* sRed = sY + R_;              // 16*32 = 512

    const int tid  = threadIdx.x;
    const int wid  = tid >> 5;          // 0..15
    const int lane = tid & 31;
    const int b0   = blockIdx.x * R_;

    for (int i = tid; i < G_ * H_; i += 512)
        sW[(i >> 7) * SWP + (i & 127)] = W_hh[i];
    for (int i = tid; i < R_ * H_; i += 512)
        sH[(i >> 7) * SWP + (i & 127)] = h0[(size_t)b0 * H_ + i];
    for (int i = tid; i < G_; i += 512) {
        sWy[i]  = W_ih[(size_t)i * (D_ + 1) + D_];   // y-feedback column
        sBhh[i] = b_hh[i];
    }
    for (int i = tid; i < H_; i += 512) sWo[i] = Wo[i];
    if (tid < R_) sY[tid] = y0[b0 + tid];
    const float bo_v = bo[0];
    __syncthreads();

    const int lg  = lane & 3;             // 0..3
    const int rg  = lane >> 2;            // 0..7
    const int c0  = (wid * 4 + lg) * 2;   // channel base (2 channels), 0..126

    const ull* sW2 = reinterpret_cast<const ull*>(sW);
    const ull* sH2 = reinterpret_cast<const ull*>(sH);
    const int bR = c0 * SWP2;             // W row bases (ull units)
    const int bZ = (H_ + c0) * SWP2;
    const int bN = (2 * H_ + c0) * SWP2;

    for (int t = 0; t < T_; t++) {
        const float* gx = g_gx + ((size_t)t * B_ + b0) * G_;

        // issue gx loads now; first use in the epilogue
        float2 xr[4], xz[4], xn[4];
        #pragma unroll
        for (int rr = 0; rr < 4; rr++) {
            const float* gxr = gx + (rg + rr * 8) * G_;
            xr[rr] = *reinterpret_cast<const float2*>(&gxr[c0]);
            xz[rr] = *reinterpret_cast<const float2*>(&gxr[H_ + c0]);
            xn[rr] = *reinterpret_cast<const float2*>(&gxr[2 * H_ + c0]);
        }

        ull ar[4][2], az[4][2], an[4][2];
        #pragma unroll
        for (int rr = 0; rr < 4; rr++)
            #pragma unroll
            for (int jj = 0; jj < 2; jj++) {
                ar[rr][jj] = 0ull; az[rr][jj] = 0ull; an[rr][jj] = 0ull;
            }

        // gh = h @ W_hh^T
        #pragma unroll 4
        for (int k2 = 0; k2 < 64; k2++) {
            ull h2[4];
            #pragma unroll
            for (int rr = 0; rr < 4; rr++)
                h2[rr] = sH2[(rg + rr * 8) * SWP2 + k2];
            #pragma unroll
            for (int jj = 0; jj < 2; jj++) {
                ull wr = sW2[bR + jj * SWP2 + k2];
                ull wz = sW2[bZ + jj * SWP2 + k2];
                ull wn = sW2[bN + jj * SWP2 + k2];
                #pragma unroll
                for (int rr = 0; rr < 4; rr++) {
                    ar[rr][jj] = ffma2(h2[rr], wr, ar[rr][jj]);
                    az[rr][jj] = ffma2(h2[rr], wz, az[rr][jj]);
                    an[rr][jj] = ffma2(h2[rr], wn, an[rr][jj]);
                }
            }
        }

        // epilogue constants (from smem, keeps regs for accum+gx)
        const float2 wy_r = *reinterpret_cast<const float2*>(&sWy[c0]);
        const float2 wy_z = *reinterpret_cast<const float2*>(&sWy[H_ + c0]);
        const float2 wy_n = *reinterpret_cast<const float2*>(&sWy[2 * H_ + c0]);
        const float2 bh_r = *reinterpret_cast<const float2*>(&sBhh[c0]);
        const float2 bh_z = *reinterpret_cast<const float2*>(&sBhh[H_ + c0]);
        const float2 bh_n = *reinterpret_cast<const float2*>(&sBhh[2 * H_ + c0]);
        const float2 wo2  = *reinterpret_cast<const float2*>(&sWo[c0]);

        float2 hnew[4];
        float  pacc[4];
        #pragma unroll
        for (int rr = 0; rr < 4; rr++) {
            int row = rg + rr * 8;
            float y = sY[row];
            float2 hp = *reinterpret_cast<const float2*>(&sH[row * SWP + c0]);

            float r0 = fast_sigmoid(xr[rr].x + y * wy_r.x + bh_r.x + f2sum(ar[rr][0]));
            float z0 = fast_sigmoid(xz[rr].x + y * wy_z.x + bh_z.x + f2sum(az[rr][0]));
            float n0 = fast_tanh  (xn[rr].x + y * wy_n.x + r0 * (bh_n.x + f2sum(an[rr][0])));
            float h0v = (1.f - z0) * n0 + z0 * hp.x;

            float r1 = fast_sigmoid(xr[rr].y + y * wy_r.y + bh_r.y + f2sum(ar[rr][1]));
            float z1 = fast_sigmoid(xz[rr].y + y * wy_z.y + bh_z.y + f2sum(az[rr][1]));
            float n1 = fast_tanh  (xn[rr].y + y * wy_n.y + r1 * (bh_n.y + f2sum(an[rr][1])));
            float h1v = (1.f - z1) * n1 + z1 * hp.y;

            hnew[rr] = make_float2(h0v, h1v);
            pacc[rr] = h0v * wo2.x + h1v * wo2.y;
        }
        __syncthreads();   // all reads of sH for this step are done

        #pragma unroll
        for (int rr = 0; rr < 4; rr++) {
            int row = rg + rr * 8;
            *reinterpret_cast<float2*>(&sH[row * SWP + c0]) = hnew[rr];
        }
        // y reduction: fold the 4 channel-lanes (same rg), then 16 warps
        #pragma unroll
        for (int rr = 0; rr < 4; rr++) {
            pacc[rr] += __shfl_xor_sync(0xffffffffu, pacc[rr], 1);
            pacc[rr] += __shfl_xor_sync(0xffffffffu, pacc[rr], 2);
        }
        if (lg == 0) {
            #pragma unroll
            for (int rr = 0; rr < 4; rr++)
                sRed[wid * R_ + rg + rr * 8] = pacc[rr];
        }
        __syncthreads();
        if (tid < R_) {
            float s = bo_v;
            #pragma unroll
            for (int w = 0; w < 16; w++) s += sRed[w * R_ + tid];
            sY[tid] = s;
            out[(size_t)(b0 + tid) * T_ + t] = s;
        }
        __syncthreads();
    }
}

// ---------------------------------------------------------------------------
extern "C" void kernel_launch(void* const* d_in, const int* in_sizes, int n_in,
                              void* d_out, int out_size)
{
    const float* feats = (const float*)d_in[0];
    const float* h0    = (const float*)d_in[1];
    const float* y0    = (const float*)d_in[2];
    const float* W_ih  = (const float*)d_in[3];
    const float* W_hh  = (const float*)d_in[4];
    const float* b_ih  = (const float*)d_in[5];
    const float* b_hh  = (const float*)d_in[6];
    const float* Wo    = (const float*)d_in[7];
    const float* bo    = (const float*)d_in[8];
    float* out = (float*)d_out;

    const int smemA = (A_NT * A_PAD + 2 * A_MT * A_PAD + A_MT * A_OP + A_NT)
                      * (int)sizeof(float);
    cudaFuncSetAttribute(gx_kernel, cudaFuncAttributeMaxDynamicSharedMemorySize, smemA);
    gx_kernel<<<148, 512, smemA>>>(feats, W_ih, b_ih);

    const int smemB = (G_ * SWP + R_ * SWP + G_ + G_ + H_ + R_ + 16 * R_)
                      * (int)sizeof(float);
    cudaFuncSetAttribute(scan_kernel, cudaFuncAttributeMaxDynamicSharedMemorySize, smemB);
    scan_kernel<<<B_ / R_, 512, smemB>>>(h0, y0, W_ih, W_hh, b_hh, Wo, bo, out);
}

// round 5
// speedup vs baseline: 1.1177x; 1.1177x over previous
#include <cuda_runtime.h>
#include <cstdint>
#include <cstddef>

#define B_ 4096
#define T_ 168
#define D_ 64
#define H_ 128
#define G_ 384   // 3*H

typedef unsigned long long ull;

__device__ __forceinline__ ull ffma2(ull a, ull b, ull c) {
    ull d;
    asm("fma.rn.f32x2 %0, %1, %2, %3;" : "=l"(d) : "l"(a), "l"(b), "l"(c));
    return d;
}
__device__ __forceinline__ float f2sum(ull v) {
    float lo = __uint_as_float((unsigned)(v & 0xffffffffull));
    float hi = __uint_as_float((unsigned)(v >> 32));
    return lo + hi;
}
__device__ __forceinline__ float fast_sigmoid(float x) {
    return __fdividef(1.f, 1.f + __expf(-x));
}
__device__ __forceinline__ float fast_tanh(float x) {
    return __fdividef(2.f, 1.f + __expf(-2.f * x)) - 1.f;
}

__device__ __forceinline__ void cpasync16(void* smem_dst, const void* gsrc) {
    unsigned saddr = (unsigned)__cvta_generic_to_shared(smem_dst);
    asm volatile("cp.async.ca.shared.global [%0], [%1], 16;\n" :: "r"(saddr), "l"(gsrc));
}
#define CP_COMMIT() asm volatile("cp.async.commit_group;\n" ::: "memory")
#define CP_WAIT(n)  asm volatile("cp.async.wait_group %0;\n" :: "n"(n) : "memory")

// Scratch: gx[t][b][g] fp32, ~1.01 GB device global.
__device__ float g_gx[(size_t)T_ * B_ * G_];

// ---------------------------------------------------------------------------
// Kernel A (unchanged from R4 measured version): near its fp32 issue floor.
// ---------------------------------------------------------------------------
#define A_NT   96
#define A_MT   128
#define A_PAD  68
#define A_OP   104

__global__ void __launch_bounds__(512, 1)
gx_kernel(const float* __restrict__ feats, const float* __restrict__ W_ih,
          const float* __restrict__ b_ih)
{
    extern __shared__ float smemA[];
    float* sW   = smemA;
    float* sF0  = sW + A_NT * A_PAD;
    float* sF1  = sF0 + A_MT * A_PAD;
    float* sOut = sF1 + A_MT * A_PAD;
    float* sB   = sOut + A_MT * A_OP;

    const int tid  = threadIdx.x;
    const int wid  = tid >> 5;
    const int lane = tid & 31;
    const int rb   = wid >> 2;
    const int gblk = wid & 3;
    const int rg   = lane >> 2;
    const int lg   = lane & 3;
    const int gloc = gblk * 24 + lg * 6;

    const int slice = blockIdx.x & 3;
    const int px    = blockIdx.x >> 2;
    const int g_base = slice * A_NT;

    for (int i = tid; i < A_NT * D_; i += 512) {
        int g = i >> 6, d = i & 63;
        sW[g * A_PAD + d] = W_ih[(size_t)(g_base + g) * (D_ + 1) + d];
    }
    for (int i = tid; i < A_NT; i += 512) sB[i] = b_ih[g_base + i];

    const int NTILES = (B_ * T_) / A_MT;
    float* sF[2] = { sF0, sF1 };

    {
        int t0 = px >> 5, bb0 = (px & 31) * A_MT;
        for (int i = 0; i < 4; i++) {
            int ci = tid + i * 512;
            int row = ci >> 4, seg = ci & 15;
            cpasync16(sF0 + row * A_PAD + seg * 4,
                      feats + ((size_t)(bb0 + row) * T_ + t0) * D_ + seg * 4);
        }
        CP_COMMIT();
    }

    int buf = 0;
    for (int mt = px; mt < NTILES; mt += 37) {
        const int t  = mt >> 5;
        const int bb = (mt & 31) * A_MT;

        int mt_next = mt + 37;
        if (mt_next < NTILES) {
            int tn = mt_next >> 5, bn = (mt_next & 31) * A_MT;
            float* dst = sF[buf ^ 1];
            for (int i = 0; i < 4; i++) {
                int ci = tid + i * 512;
                int row = ci >> 4, seg = ci & 15;
                cpasync16(dst + row * A_PAD + seg * 4,
                          feats + ((size_t)(bn + row) * T_ + tn) * D_ + seg * 4);
            }
            CP_COMMIT();
            CP_WAIT(1);
        } else {
            CP_WAIT(0);
        }
        __syncthreads();

        const ulonglong2* sF16 = reinterpret_cast<const ulonglong2*>(sF[buf]);
        const ulonglong2* sW16 = reinterpret_cast<const ulonglong2*>(sW);

        ull acc[4][6];
        #pragma unroll
        for (int a = 0; a < 4; a++)
            #pragma unroll
            for (int u = 0; u < 6; u++) acc[a][u] = 0ull;

        #pragma unroll 4
        for (int k4 = 0; k4 < 16; k4++) {
            ulonglong2 f[4];
            #pragma unroll
            for (int rr = 0; rr < 4; rr++)
                f[rr] = sF16[(rb * 32 + rg + rr * 8) * 17 + k4];
            #pragma unroll
            for (int u = 0; u < 6; u++) {
                ulonglong2 w = sW16[(gloc + u) * 17 + k4];
                #pragma unroll
                for (int rr = 0; rr < 4; rr++) {
                    acc[rr][u] = ffma2(f[rr].x, w.x, acc[rr][u]);
                    acc[rr][u] = ffma2(f[rr].y, w.y, acc[rr][u]);
                }
            }
        }

        #pragma unroll
        for (int rr = 0; rr < 4; rr++) {
            int row = rb * 32 + rg + rr * 8;
            float* o = &sOut[row * A_OP + gloc];
            #pragma unroll
            for (int v = 0; v < 3; v++) {
                float2 p;
                p.x = f2sum(acc[rr][v * 2 + 0]) + sB[gloc + v * 2 + 0];
                p.y = f2sum(acc[rr][v * 2 + 1]) + sB[gloc + v * 2 + 1];
                *reinterpret_cast<float2*>(o + v * 2) = p;
            }
        }
        __syncthreads();

        for (int i = 0; i < 6; i++) {
            int ci = tid + i * 512;
            int row = ci / 24, seg = ci - row * 24;
            float4 v = *reinterpret_cast<const float4*>(&sOut[row * A_OP + seg * 4]);
            *reinterpret_cast<float4*>(
                &g_gx[((size_t)t * B_ + bb + row) * G_ + g_base + seg * 4]) = v;
        }
        buf ^= 1;
    }
}

// ---------------------------------------------------------------------------
// Kernel B: persistent GRU scan, crossbar-optimized.
// 128 blocks x 256 threads (8 warps). Thread tile: r=8 rows x c=2 channels
// x {r,z,n} = 48 packed accumulators. Crossbar model: 16384*(1/c+3/r) =
// 14,336 cyc/step (was 20,480 at r=4,c=2).
// Lane map: lg = lane&7 (channel pairs), rg = lane>>3 (row groups).
//   h LDS.64: rows rg+4*rr -> 4 distinct addrs, delta = 130 words = 2 banks,
//             conflict-free, 8-way bcast.
//   W LDS.64: channels c0 = wid*16+lg*2 -> 8 distinct addrs, delta = 260
//             words = 4 banks mod 32 -> 8 distinct banks, conflict-free.
// gx prefetched into registers at loop top, consumed in epilogue.
// ---------------------------------------------------------------------------
#define R_    32
#define SWP   130
#define SWP2  65

__global__ void __launch_bounds__(256, 1)
scan_kernel(const float* __restrict__ h0, const float* __restrict__ y0,
            const float* __restrict__ W_ih, const float* __restrict__ W_hh,
            const float* __restrict__ b_hh, const float* __restrict__ Wo,
            const float* __restrict__ bo, float* __restrict__ out)
{
    extern __shared__ float smem[];
    float* sW   = smem;                 // 384*130 = 49920
    float* sH   = sW + G_ * SWP;        // 32*130  = 4160
    float* sWy  = sH + R_ * SWP;        // 384
    float* sBhh = sWy + G_;             // 384
    float* sWo  = sBhh + G_;            // 128
    float* sY   = sWo + H_;             // 32
    float* sRed = sY + R_;              // 8*32 = 256

    const int tid  = threadIdx.x;
    const int wid  = tid >> 5;          // 0..7
    const int lane = tid & 31;
    const int b0   = blockIdx.x * R_;

    for (int i = tid; i < G_ * H_; i += 256)
        sW[(i >> 7) * SWP + (i & 127)] = W_hh[i];
    for (int i = tid; i < R_ * H_; i += 256)
        sH[(i >> 7) * SWP + (i & 127)] = h0[(size_t)b0 * H_ + i];
    for (int i = tid; i < G_; i += 256) {
        sWy[i]  = W_ih[(size_t)i * (D_ + 1) + D_];
        sBhh[i] = b_hh[i];
    }
    for (int i = tid; i < H_; i += 256) sWo[i] = Wo[i];
    if (tid < R_) sY[tid] = y0[b0 + tid];
    const float bo_v = bo[0];
    __syncthreads();

    const int lg  = lane & 7;             // 0..7 channel-pair group
    const int rg  = lane >> 3;            // 0..3 row group
    const int c0  = wid * 16 + lg * 2;    // channels c0, c0+1

    const ull* sW2 = reinterpret_cast<const ull*>(sW);
    const ull* sH2 = reinterpret_cast<const ull*>(sH);
    const int bR0 = c0 * SWP2;
    const int bR1 = (c0 + 1) * SWP2;
    const int bZ0 = (H_ + c0) * SWP2;
    const int bZ1 = (H_ + c0 + 1) * SWP2;
    const int bN0 = (2 * H_ + c0) * SWP2;
    const int bN1 = (2 * H_ + c0 + 1) * SWP2;

    for (int t = 0; t < T_; t++) {
        const float* gx = g_gx + ((size_t)t * B_ + b0) * G_;

        // gx prefetch: first use ~14k cycles later in the epilogue
        float2 xr[8], xz[8], xn[8];
        #pragma unroll
        for (int rr = 0; rr < 8; rr++) {
            const float* gxr = gx + (rg + 4 * rr) * G_;
            xr[rr] = *reinterpret_cast<const float2*>(&gxr[c0]);
            xz[rr] = *reinterpret_cast<const float2*>(&gxr[H_ + c0]);
            xn[rr] = *reinterpret_cast<const float2*>(&gxr[2 * H_ + c0]);
        }

        ull ar[8][2], az[8][2], an[8][2];
        #pragma unroll
        for (int rr = 0; rr < 8; rr++)
            #pragma unroll
            for (int jj = 0; jj < 2; jj++) {
                ar[rr][jj] = 0ull; az[rr][jj] = 0ull; an[rr][jj] = 0ull;
            }

        // gh = h @ W_hh^T  (crossbar-bound mainloop, 14 LDS.64 / 48 FFMA2 per k2)
        #pragma unroll 2
        for (int k2 = 0; k2 < 64; k2++) {
            ull h2[8];
            #pragma unroll
            for (int rr = 0; rr < 8; rr++)
                h2[rr] = sH2[(rg + 4 * rr) * SWP2 + k2];

            ull wr0 = sW2[bR0 + k2], wr1 = sW2[bR1 + k2];
            ull wz0 = sW2[bZ0 + k2], wz1 = sW2[bZ1 + k2];
            ull wn0 = sW2[bN0 + k2], wn1 = sW2[bN1 + k2];
            #pragma unroll
            for (int rr = 0; rr < 8; rr++) {
                ar[rr][0] = ffma2(h2[rr], wr0, ar[rr][0]);
                ar[rr][1] = ffma2(h2[rr], wr1, ar[rr][1]);
                az[rr][0] = ffma2(h2[rr], wz0, az[rr][0]);
                az[rr][1] = ffma2(h2[rr], wz1, az[rr][1]);
                an[rr][0] = ffma2(h2[rr], wn0, an[rr][0]);
                an[rr][1] = ffma2(h2[rr], wn1, an[rr][1]);
            }
        }

        // epilogue constants from smem
        const float2 wy_r = *reinterpret_cast<const float2*>(&sWy[c0]);
        const float2 wy_z = *reinterpret_cast<const float2*>(&sWy[H_ + c0]);
        const float2 wy_n = *reinterpret_cast<const float2*>(&sWy[2 * H_ + c0]);
        const float2 bh_r = *reinterpret_cast<const float2*>(&sBhh[c0]);
        const float2 bh_z = *reinterpret_cast<const float2*>(&sBhh[H_ + c0]);
        const float2 bh_n = *reinterpret_cast<const float2*>(&sBhh[2 * H_ + c0]);
        const float2 wo2  = *reinterpret_cast<const float2*>(&sWo[c0]);

        float2 hnew[8];
        float  pacc[8];
        #pragma unroll
        for (int rr = 0; rr < 8; rr++) {
            int row = rg + 4 * rr;
            float y = sY[row];
            float2 hp = *reinterpret_cast<const float2*>(&sH[row * SWP + c0]);

            float r0 = fast_sigmoid(xr[rr].x + y * wy_r.x + bh_r.x + f2sum(ar[rr][0]));
            float z0 = fast_sigmoid(xz[rr].x + y * wy_z.x + bh_z.x + f2sum(az[rr][0]));
            float n0 = fast_tanh  (xn[rr].x + y * wy_n.x + r0 * (bh_n.x + f2sum(an[rr][0])));
            float h0v = (1.f - z0) * n0 + z0 * hp.x;

            float r1 = fast_sigmoid(xr[rr].y + y * wy_r.y + bh_r.y + f2sum(ar[rr][1]));
            float z1 = fast_sigmoid(xz[rr].y + y * wy_z.y + bh_z.y + f2sum(az[rr][1]));
            float n1 = fast_tanh  (xn[rr].y + y * wy_n.y + r1 * (bh_n.y + f2sum(an[rr][1])));
            float h1v = (1.f - z1) * n1 + z1 * hp.y;

            hnew[rr] = make_float2(h0v, h1v);
            pacc[rr] = h0v * wo2.x + h1v * wo2.y;
        }
        __syncthreads();   // all reads of sH for this step done

        #pragma unroll
        for (int rr = 0; rr < 8; rr++) {
            int row = rg + 4 * rr;
            *reinterpret_cast<float2*>(&sH[row * SWP + c0]) = hnew[rr];
        }
        // y reduction: fold 8 lg lanes (same rg) via shfl, then 8 warps
        #pragma unroll
        for (int rr = 0; rr < 8; rr++) {
            pacc[rr] += __shfl_xor_sync(0xffffffffu, pacc[rr], 1);
            pacc[rr] += __shfl_xor_sync(0xffffffffu, pacc[rr], 2);
            pacc[rr] += __shfl_xor_sync(0xffffffffu, pacc[rr], 4);
        }
        if (lg == 0) {
            #pragma unroll
            for (int rr = 0; rr < 8; rr++)
                sRed[wid * R_ + rg + 4 * rr] = pacc[rr];
        }
        __syncthreads();
        if (tid < R_) {
            float s = bo_v;
            #pragma unroll
            for (int w = 0; w < 8; w++) s += sRed[w * R_ + tid];
            sY[tid] = s;
            out[(size_t)(b0 + tid) * T_ + t] = s;
        }
        __syncthreads();
    }
}

// ---------------------------------------------------------------------------
extern "C" void kernel_launch(void* const* d_in, const int* in_sizes, int n_in,
                              void* d_out, int out_size)
{
    const float* feats = (const float*)d_in[0];
    const float* h0    = (const float*)d_in[1];
    const float* y0    = (const float*)d_in[2];
    const float* W_ih  = (const float*)d_in[3];
    const float* W_hh  = (const float*)d_in[4];
    const float* b_ih  = (const float*)d_in[5];
    const float* b_hh  = (const float*)d_in[6];
    const float* Wo    = (const float*)d_in[7];
    const float* bo    = (const float*)d_in[8];
    float* out = (float*)d_out;

    const int smemA = (A_NT * A_PAD + 2 * A_MT * A_PAD + A_MT * A_OP + A_NT)
                      * (int)sizeof(float);
    cudaFuncSetAttribute(gx_kernel, cudaFuncAttributeMaxDynamicSharedMemorySize, smemA);
    gx_kernel<<<148, 512, smemA>>>(feats, W_ih, b_ih);

    const int smemB = (G_ * SWP + R_ * SWP + G_ + G_ + H_ + R_ + 8 * R_)
                      * (int)sizeof(float);
    cudaFuncSetAttribute(scan_kernel, cudaFuncAttributeMaxDynamicSharedMemorySize, smemB);
    scan_kernel<<<B_ / R_, 256, smemB>>>(h0, y0, W_ih, W_hh, b_hh, Wo, bo, out);
}